// round 11
// baseline (speedup 1.0000x reference)
#include <cuda_runtime.h>
#include <math.h>
#include <stdint.h>

#define NT 16384
#define HID 1024
#define NH 512
#define G3 1536
#define SCAN_CTAS 32

// ---------------- scratch (device globals; no allocation) ----------------
__device__ __align__(16) float d_xn[16384 * 1024];   // layernormed x
__device__ __align__(16) float d_ig[16384 * 1536];   // igates
__device__ __align__(16) float d_hs[16384 * 512];    // h trajectory
__device__ __align__(16) float d_g[16384 * 512];     // gelu(hs)
__device__ __align__(16) float d_y1[16384 * 1024];
__device__ __align__(16) float d_y2[16384 * 1024];

// tagged h exchange: g_hx8[buf][j] = (f32 h[j] low 32b, u32 tag high 32b).
// RELAXED gpu-scope ops: strong => single-copy atomic; unordered => polls pipeline.
__device__ __align__(16) unsigned long long g_hx8[2][NH];

// ---------------- small helpers ----------------
__device__ __forceinline__ void ffma2(unsigned long long& d, unsigned long long a, unsigned long long b) {
    asm volatile("fma.rn.f32x2 %0, %1, %2, %0;" : "+l"(d) : "l"(a), "l"(b));
}
__device__ __forceinline__ unsigned long long pk2(float lo, float hi) {
    unsigned long long r;
    asm("mov.b64 %0, {%1, %2};" : "=l"(r) : "f"(lo), "f"(hi));
    return r;
}
__device__ __forceinline__ float2 up2(unsigned long long v) {
    float lo, hi;
    asm("mov.b64 {%0, %1}, %2;" : "=f"(lo), "=f"(hi) : "l"(v));
    return make_float2(lo, hi);
}
__device__ __forceinline__ unsigned long long pkht(float h, unsigned tag) {
    unsigned long long r;
    asm("mov.b64 %0, {%1, %2};" : "=l"(r) : "f"(h), "r"(tag));
    return r;
}
__device__ __forceinline__ unsigned hx_tag(unsigned long long v) { return (unsigned)(v >> 32); }
__device__ __forceinline__ float hx_val(unsigned long long v) {
    float h; unsigned t;
    asm("mov.b64 {%0, %1}, %2;" : "=f"(h), "=r"(t) : "l"(v));
    (void)t;
    return h;
}
__device__ __forceinline__ float sigmoid_acc(float x) { return 1.0f / (1.0f + expf(-x)); }
__device__ __forceinline__ float sigmoid_fast(float x) {
    return __fdividef(1.0f, 1.0f + __expf(-x));
}
__device__ __forceinline__ float tanh_fast(float x) {
    // tanh(x) = 2*sigmoid(2x) - 1, same MUFU path as sigmoid_fast (~1e-6 rel err)
    return __fdividef(2.0f, 1.0f + __expf(-2.0f * x)) - 1.0f;
}

// strong relaxed publish / poll (gpu scope): atomic, unordered, pipelineable
__device__ __forceinline__ void st_rlx_u64(unsigned long long* p, unsigned long long v) {
    asm volatile("st.relaxed.gpu.global.u64 [%0], %1;" :: "l"(p), "l"(v) : "memory");
}
__device__ __forceinline__ unsigned long long ld_rlx_u64(const unsigned long long* p) {
    unsigned long long v;
    asm volatile("ld.relaxed.gpu.global.u64 %0, [%1];" : "=l"(v) : "l"(p) : "memory");
    return v;
}

// ---------------- LayerNorm ----------------
__global__ __launch_bounds__(256) void ln_kernel(const float* __restrict__ x,
                                                 const float* __restrict__ w,
                                                 const float* __restrict__ bb,
                                                 float* __restrict__ xn) {
    const int row = blockIdx.x;
    const int tid = threadIdx.x;
    const float4 v = ((const float4*)(x + (size_t)row * HID))[tid];
    float s = v.x + v.y + v.z + v.w;
    float q = v.x * v.x + v.y * v.y + v.z * v.z + v.w * v.w;
#pragma unroll
    for (int off = 16; off; off >>= 1) {
        s += __shfl_xor_sync(0xffffffffu, s, off);
        q += __shfl_xor_sync(0xffffffffu, q, off);
    }
    __shared__ float rs[8], rq[8];
    __shared__ float mu_s, rstd_s;
    const int wid = tid >> 5, lane = tid & 31;
    if (lane == 0) { rs[wid] = s; rq[wid] = q; }
    __syncthreads();
    if (tid == 0) {
        float S = 0.f, Q = 0.f;
#pragma unroll
        for (int i = 0; i < 8; i++) { S += rs[i]; Q += rq[i]; }
        float mu = S * (1.0f / HID);
        float var = Q * (1.0f / HID) - mu * mu;
        mu_s = mu;
        rstd_s = rsqrtf(var + 1e-5f);
    }
    __syncthreads();
    const float mu = mu_s, rstd = rstd_s;
    const float4 wv = ((const float4*)w)[tid];
    const float4 bv = ((const float4*)bb)[tid];
    float4 o;
    o.x = (v.x - mu) * rstd * wv.x + bv.x;
    o.y = (v.y - mu) * rstd * wv.y + bv.y;
    o.z = (v.z - mu) * rstd * wv.z + bv.z;
    o.w = (v.w - mu) * rstd * wv.w + bv.w;
    ((float4*)(xn + (size_t)row * HID))[tid] = o;
}

// ---------------- SGEMM: C[M,N] = A[M,K] * B[N,K]^T + bias[N] ----------------
#define BM 128
#define BN 128
#define BKK 16
__global__ __launch_bounds__(256) void sgemm_nt(const float* __restrict__ A,
                                                const float* __restrict__ B,
                                                const float* __restrict__ bias,
                                                float* __restrict__ C,
                                                int M, int N, int K) {
    __shared__ float As[BKK][BM];
    __shared__ float Bs[BKK][BN];
    const int tid = threadIdx.x;
    const int bm = blockIdx.y, bn = blockIdx.x;
    const float* Ab = A + (size_t)bm * BM * K;
    const float* Bb = B + (size_t)bn * BN * K;
    const int lrow = tid >> 2;         // 0..63
    const int lcol = (tid & 3) << 2;   // 0,4,8,12
    const int tx = tid & 15, ty = tid >> 4;
    float acc[8][8];
#pragma unroll
    for (int i = 0; i < 8; i++)
#pragma unroll
        for (int jj = 0; jj < 8; jj++) acc[i][jj] = 0.f;

    for (int k0 = 0; k0 < K; k0 += BKK) {
        const float4 a0 = *(const float4*)(Ab + (size_t)lrow * K + k0 + lcol);
        const float4 a1 = *(const float4*)(Ab + (size_t)(lrow + 64) * K + k0 + lcol);
        const float4 b0 = *(const float4*)(Bb + (size_t)lrow * K + k0 + lcol);
        const float4 b1 = *(const float4*)(Bb + (size_t)(lrow + 64) * K + k0 + lcol);
        __syncthreads();
        As[lcol + 0][lrow] = a0.x; As[lcol + 1][lrow] = a0.y;
        As[lcol + 2][lrow] = a0.z; As[lcol + 3][lrow] = a0.w;
        As[lcol + 0][lrow + 64] = a1.x; As[lcol + 1][lrow + 64] = a1.y;
        As[lcol + 2][lrow + 64] = a1.z; As[lcol + 3][lrow + 64] = a1.w;
        Bs[lcol + 0][lrow] = b0.x; Bs[lcol + 1][lrow] = b0.y;
        Bs[lcol + 2][lrow] = b0.z; Bs[lcol + 3][lrow] = b0.w;
        Bs[lcol + 0][lrow + 64] = b1.x; Bs[lcol + 1][lrow + 64] = b1.y;
        Bs[lcol + 2][lrow + 64] = b1.z; Bs[lcol + 3][lrow + 64] = b1.w;
        __syncthreads();
#pragma unroll
        for (int k = 0; k < BKK; ++k) {
            float ar[8], br[8];
            *(float4*)&ar[0] = *(const float4*)&As[k][ty * 8];
            *(float4*)&ar[4] = *(const float4*)&As[k][ty * 8 + 4];
            *(float4*)&br[0] = *(const float4*)&Bs[k][tx * 8];
            *(float4*)&br[4] = *(const float4*)&Bs[k][tx * 8 + 4];
#pragma unroll
            for (int i = 0; i < 8; i++)
#pragma unroll
                for (int jj = 0; jj < 8; jj++) acc[i][jj] += ar[i] * br[jj];
        }
    }
#pragma unroll
    for (int i = 0; i < 8; i++) {
        const size_t row = (size_t)bm * BM + ty * 8 + i;
        float* Cr = C + row * N + bn * BN + tx * 8;
        const float* bp = bias + bn * BN + tx * 8;
#pragma unroll
        for (int jj = 0; jj < 8; jj++) Cr[jj] = acc[i][jj] + bp[jj];
    }
}

// ---------------- scan init: seed tag buffers (runs before scan each launch) ----------------
__global__ void scan_init_kernel() {
    const int i = threadIdx.x;  // 512 threads
    st_rlx_u64(&g_hx8[0][i], pkht(0.0f, 0u));           // h(0)=0, tag 0
    st_rlx_u64(&g_hx8[1][i], pkht(0.0f, 0xFFFFFFFFu));  // sentinel
}

// ---------------- persistent GRU scan: 32 CTAs, relaxed-atomic tagged L2 exchange ----------------
// Each CTA owns 16 state indices j = blk*16 + (tid>>4); 16 lanes per gate-group.
__global__ __launch_bounds__(256, 1) void gru_scan(const float* __restrict__ w_hh,
                                                   const float* __restrict__ b_n,
                                                   const float* __restrict__ igates,
                                                   float* __restrict__ hs,
                                                   float* h_final) {
    __shared__ __align__(16) float sh_h[2][NH];   // double-buffered staged h

    const int tid = threadIdx.x;
    const int gidx = tid >> 4, li = tid & 15;
    const int blk = blockIdx.x;
    const int j = blk * 16 + gidx;

    // preload weight slice: rows (j, 512+j, 1024+j), cols li*4 + m*64 + {0..3}, m=0..7
    unsigned long long wr[16], wz[16], wn[16];
    {
        const float* br_ = w_hh + (size_t)j * NH + li * 4;
        const float* bz_ = w_hh + (size_t)(NH + j) * NH + li * 4;
        const float* bn_ = w_hh + (size_t)(2 * NH + j) * NH + li * 4;
#pragma unroll
        for (int m = 0; m < 8; m++) {
            float4 v = *(const float4*)(br_ + m * 64);
            wr[2 * m] = pk2(v.x, v.y); wr[2 * m + 1] = pk2(v.z, v.w);
            v = *(const float4*)(bz_ + m * 64);
            wz[2 * m] = pk2(v.x, v.y); wz[2 * m + 1] = pk2(v.z, v.w);
            v = *(const float4*)(bn_ + m * 64);
            wn[2 * m] = pk2(v.x, v.y); wn[2 * m + 1] = pk2(v.z, v.w);
        }
    }
    const float bnj = b_n[j];

    float igr = 0.f, igz = 0.f, ign = 0.f;
    if (li == 0) {
        igr = igates[j];
        igz = igates[NH + j];
        ign = igates[2 * NH + j];
    }

    for (int t = 0; t < NT; ++t) {
        const int buf = t & 1;
        // ---- consume: relaxed-poll my two (h, tag) words until both tags == t ----
        {
            const unsigned long long* gp = &g_hx8[buf][2 * tid];
            unsigned long long vx = ld_rlx_u64(gp);
            unsigned long long vy = ld_rlx_u64(gp + 1);
            while (hx_tag(vx) != (unsigned)t || hx_tag(vy) != (unsigned)t) {
                vx = ld_rlx_u64(gp);
                vy = ld_rlx_u64(gp + 1);
            }
            ((float2*)sh_h[buf])[tid] = make_float2(hx_val(vx), hx_val(vy));
        }
        __syncthreads();

        // ---- matvec on staged h: 16 lanes per j, each lane covers 32 h values ----
        unsigned long long ar = 0ULL, az = 0ULL, an = 0ULL;
        const ulonglong2* hv2 = (const ulonglong2*)sh_h[buf];
#pragma unroll
        for (int m = 0; m < 8; m++) {
            const ulonglong2 h2 = hv2[li + 16 * m];
            ffma2(ar, wr[2 * m], h2.x); ffma2(ar, wr[2 * m + 1], h2.y);
            ffma2(az, wz[2 * m], h2.x); ffma2(az, wz[2 * m + 1], h2.y);
            ffma2(an, wn[2 * m], h2.x); ffma2(an, wn[2 * m + 1], h2.y);
        }
        float2 f;
        f = up2(ar); float sr = f.x + f.y;
        f = up2(az); float sz = f.x + f.y;
        f = up2(an); float sn = f.x + f.y;
#pragma unroll
        for (int off = 8; off; off >>= 1) {
            sr += __shfl_xor_sync(0xffffffffu, sr, off);
            sz += __shfl_xor_sync(0xffffffffu, sz, off);
            sn += __shfl_xor_sync(0xffffffffu, sn, off);
        }

        if (li == 0) {
            const float r = sigmoid_fast(igr + sr);
            const float z = sigmoid_fast(igz + sz);
            const float n = tanh_fast(ign + r * (sn + bnj));
            const float hprev = sh_h[buf][j];
            const float hnew = n + z * (hprev - n);
            if (t < NT - 1) {
                // publish FIRST (unordered => no stall behind other stores)
                st_rlx_u64(&g_hx8[buf ^ 1][j], pkht(hnew, (unsigned)(t + 1)));
            }
            hs[(size_t)t * NH + j] = hnew;
            if (t == NT - 1) {
                if (h_final != nullptr) h_final[j] = hnew;
            } else {
                const float* igp = igates + (size_t)(t + 1) * G3;
                igr = igp[j]; igz = igp[NH + j]; ign = igp[2 * NH + j];
            }
        }
    }
}

// ---------------- gelu (tanh approx, matches jax default) ----------------
__global__ __launch_bounds__(256) void gelu_kernel(const float* __restrict__ in,
                                                   float* __restrict__ outp) {
    const size_t i = (size_t)blockIdx.x * 256 + threadIdx.x;
    const float4 v = ((const float4*)in)[i];
    const float c0 = 0.7978845608028654f, c1 = 0.044715f;
    float4 o;
    o.x = 0.5f * v.x * (1.0f + tanhf(c0 * (v.x + c1 * v.x * v.x * v.x)));
    o.y = 0.5f * v.y * (1.0f + tanhf(c0 * (v.y + c1 * v.y * v.y * v.y)));
    o.z = 0.5f * v.z * (1.0f + tanhf(c0 * (v.z + c1 * v.z * v.z * v.z)));
    o.w = 0.5f * v.w * (1.0f + tanhf(c0 * (v.w + c1 * v.w * v.w * v.w)));
    ((float4*)outp)[i] = o;
}

// ---------------- final combine: out = x + y1 * sigmoid(y2) ----------------
__global__ __launch_bounds__(256) void combine_kernel(const float* __restrict__ x,
                                                      const float* __restrict__ y1,
                                                      const float* __restrict__ y2,
                                                      float* __restrict__ outp) {
    const size_t i = (size_t)blockIdx.x * 256 + threadIdx.x;
    const float4 xv = ((const float4*)x)[i];
    const float4 a = ((const float4*)y1)[i];
    const float4 s = ((const float4*)y2)[i];
    float4 o;
    o.x = xv.x + a.x * sigmoid_acc(s.x);
    o.y = xv.y + a.y * sigmoid_acc(s.y);
    o.z = xv.z + a.z * sigmoid_acc(s.z);
    o.w = xv.w + a.w * sigmoid_acc(s.w);
    ((float4*)outp)[i] = o;
}

// ---------------- launch ----------------
extern "C" void kernel_launch(void* const* d_in, const int* in_sizes, int n_in,
                              void* d_out, int out_size) {
    const float* x     = (const float*)d_in[0];
    const float* w_ih  = (const float*)d_in[1];
    const float* w_hh  = (const float*)d_in[2];
    const float* b     = (const float*)d_in[3];
    const float* b_n   = (const float*)d_in[4];
    const float* out_w  = (const float*)d_in[5];
    const float* out_b  = (const float*)d_in[6];
    const float* out2_w = (const float*)d_in[7];
    const float* out2_b = (const float*)d_in[8];
    const float* ln_w  = (const float*)d_in[9];
    const float* ln_b  = (const float*)d_in[10];

    float* outp = (float*)d_out;
    float* hfin = nullptr;
    float* ybase = outp;
    if (out_size == 512 + 16384 * 1024) {  // tuple (h_final, y) flattened
        hfin = outp;
        ybase = outp + 512;
    }

    void *p_xn, *p_ig, *p_hs, *p_g, *p_y1, *p_y2;
    cudaGetSymbolAddress(&p_xn, d_xn);
    cudaGetSymbolAddress(&p_ig, d_ig);
    cudaGetSymbolAddress(&p_hs, d_hs);
    cudaGetSymbolAddress(&p_g, d_g);
    cudaGetSymbolAddress(&p_y1, d_y1);
    cudaGetSymbolAddress(&p_y2, d_y2);

    scan_init_kernel<<<1, 512>>>();   // reseed tag buffers (replay-safe)
    ln_kernel<<<NT, 256>>>(x, ln_w, ln_b, (float*)p_xn);
    sgemm_nt<<<dim3(G3 / BN, NT / BM), 256>>>((const float*)p_xn, w_ih, b,
                                              (float*)p_ig, NT, G3, HID);
    gru_scan<<<SCAN_CTAS, 256>>>(w_hh, b_n, (const float*)p_ig, (float*)p_hs, hfin);
    gelu_kernel<<<(NT * NH) / (4 * 256), 256>>>((const float*)p_hs, (float*)p_g);
    sgemm_nt<<<dim3(HID / BN, NT / BM), 256>>>((const float*)p_g, out_w, out_b,
                                               (float*)p_y1, NT, HID, NH);
    sgemm_nt<<<dim3(HID / BN, NT / BM), 256>>>((const float*)p_g, out2_w, out2_b,
                                               (float*)p_y2, NT, HID, NH);
    combine_kernel<<<(NT * HID) / (4 * 256), 256>>>(x, (const float*)p_y1,
                                                    (const float*)p_y2, ybase);
}

// round 15
// speedup vs baseline: 1.0804x; 1.0804x over previous
#include <cuda_runtime.h>
#include <math.h>
#include <stdint.h>

#define NT 16384
#define HID 1024
#define NH 512
#define G3 1536
#define SCAN_CTAS 16

// ---------------- scratch (device globals; no allocation) ----------------
__device__ __align__(16) float d_xn[16384 * 1024];   // layernormed x
__device__ __align__(16) float d_ig[16384 * 1536];   // igates
__device__ __align__(16) float d_hs[16384 * 512];    // h trajectory
__device__ __align__(16) float d_g[16384 * 512];     // gelu(hs)
__device__ __align__(16) float d_y1[16384 * 1024];
__device__ __align__(16) float d_y2[16384 * 1024];

// tagged h exchange: g_hx8[buf][j] = (f32 h[j] low 32b, u32 tag high 32b).
// RELAXED gpu-scope ops: strong => single-copy atomic; unordered => polls pipeline.
__device__ __align__(16) unsigned long long g_hx8[2][NH];

// ---------------- small helpers ----------------
__device__ __forceinline__ void ffma2(unsigned long long& d, unsigned long long a, unsigned long long b) {
    asm volatile("fma.rn.f32x2 %0, %1, %2, %0;" : "+l"(d) : "l"(a), "l"(b));
}
__device__ __forceinline__ unsigned long long pk2(float lo, float hi) {
    unsigned long long r;
    asm("mov.b64 %0, {%1, %2};" : "=l"(r) : "f"(lo), "f"(hi));
    return r;
}
__device__ __forceinline__ float2 up2(unsigned long long v) {
    float lo, hi;
    asm("mov.b64 {%0, %1}, %2;" : "=f"(lo), "=f"(hi) : "l"(v));
    return make_float2(lo, hi);
}
__device__ __forceinline__ unsigned long long pkht(float h, unsigned tag) {
    unsigned long long r;
    asm("mov.b64 %0, {%1, %2};" : "=l"(r) : "f"(h), "r"(tag));
    return r;
}
__device__ __forceinline__ unsigned hx_tag(unsigned long long v) { return (unsigned)(v >> 32); }
__device__ __forceinline__ float hx_val(unsigned long long v) {
    float h; unsigned t;
    asm("mov.b64 {%0, %1}, %2;" : "=f"(h), "=r"(t) : "l"(v));
    (void)t;
    return h;
}
__device__ __forceinline__ float sigmoid_acc(float x) { return 1.0f / (1.0f + expf(-x)); }
__device__ __forceinline__ float sigmoid_fast(float x) {
    return __fdividef(1.0f, 1.0f + __expf(-x));
}
__device__ __forceinline__ float tanh_fast(float x) {
    // tanh(x) = 2*sigmoid(2x) - 1, MUFU path (~1e-6 rel err; validated R11)
    return __fdividef(2.0f, 1.0f + __expf(-2.0f * x)) - 1.0f;
}

// strong relaxed publish / poll (gpu scope): atomic, unordered, pipelineable
__device__ __forceinline__ void st_rlx_u64(unsigned long long* p, unsigned long long v) {
    asm volatile("st.relaxed.gpu.global.u64 [%0], %1;" :: "l"(p), "l"(v) : "memory");
}
__device__ __forceinline__ unsigned long long ld_rlx_u64(const unsigned long long* p) {
    unsigned long long v;
    asm volatile("ld.relaxed.gpu.global.u64 %0, [%1];" : "=l"(v) : "l"(p) : "memory");
    return v;
}

// ---------------- LayerNorm ----------------
__global__ __launch_bounds__(256) void ln_kernel(const float* __restrict__ x,
                                                 const float* __restrict__ w,
                                                 const float* __restrict__ bb,
                                                 float* __restrict__ xn) {
    const int row = blockIdx.x;
    const int tid = threadIdx.x;
    const float4 v = ((const float4*)(x + (size_t)row * HID))[tid];
    float s = v.x + v.y + v.z + v.w;
    float q = v.x * v.x + v.y * v.y + v.z * v.z + v.w * v.w;
#pragma unroll
    for (int off = 16; off; off >>= 1) {
        s += __shfl_xor_sync(0xffffffffu, s, off);
        q += __shfl_xor_sync(0xffffffffu, q, off);
    }
    __shared__ float rs[8], rq[8];
    __shared__ float mu_s, rstd_s;
    const int wid = tid >> 5, lane = tid & 31;
    if (lane == 0) { rs[wid] = s; rq[wid] = q; }
    __syncthreads();
    if (tid == 0) {
        float S = 0.f, Q = 0.f;
#pragma unroll
        for (int i = 0; i < 8; i++) { S += rs[i]; Q += rq[i]; }
        float mu = S * (1.0f / HID);
        float var = Q * (1.0f / HID) - mu * mu;
        mu_s = mu;
        rstd_s = rsqrtf(var + 1e-5f);
    }
    __syncthreads();
    const float mu = mu_s, rstd = rstd_s;
    const float4 wv = ((const float4*)w)[tid];
    const float4 bv = ((const float4*)bb)[tid];
    float4 o;
    o.x = (v.x - mu) * rstd * wv.x + bv.x;
    o.y = (v.y - mu) * rstd * wv.y + bv.y;
    o.z = (v.z - mu) * rstd * wv.z + bv.z;
    o.w = (v.w - mu) * rstd * wv.w + bv.w;
    ((float4*)(xn + (size_t)row * HID))[tid] = o;
}

// ---------------- SGEMM (packed f32x2): C[M,N] = A[M,K] * B[N,K]^T + bias[N] ----------------
#define BM 128
#define BN 128
#define BKK 16
__global__ __launch_bounds__(256) void sgemm_nt(const float* __restrict__ A,
                                                const float* __restrict__ B,
                                                const float* __restrict__ bias,
                                                float* __restrict__ C,
                                                int M, int N, int K) {
    __shared__ __align__(16) float As[BKK][BM];
    __shared__ __align__(16) float Bs[BKK][BN];
    const int tid = threadIdx.x;
    const int bm = blockIdx.y, bn = blockIdx.x;
    const float* Ab = A + (size_t)bm * BM * K;
    const float* Bb = B + (size_t)bn * BN * K;
    const int lrow = tid >> 2;         // 0..63
    const int lcol = (tid & 3) << 2;   // 0,4,8,12
    const int tx = tid & 15, ty = tid >> 4;
    // packed accumulators: acc2[i][p] holds columns (tx*8+2p, tx*8+2p+1) for row ty*8+i
    unsigned long long acc2[8][4];
#pragma unroll
    for (int i = 0; i < 8; i++)
#pragma unroll
        for (int p = 0; p < 4; p++) acc2[i][p] = 0ULL;

    for (int k0 = 0; k0 < K; k0 += BKK) {
        const float4 a0 = *(const float4*)(Ab + (size_t)lrow * K + k0 + lcol);
        const float4 a1 = *(const float4*)(Ab + (size_t)(lrow + 64) * K + k0 + lcol);
        const float4 b0 = *(const float4*)(Bb + (size_t)lrow * K + k0 + lcol);
        const float4 b1 = *(const float4*)(Bb + (size_t)(lrow + 64) * K + k0 + lcol);
        __syncthreads();
        As[lcol + 0][lrow] = a0.x; As[lcol + 1][lrow] = a0.y;
        As[lcol + 2][lrow] = a0.z; As[lcol + 3][lrow] = a0.w;
        As[lcol + 0][lrow + 64] = a1.x; As[lcol + 1][lrow + 64] = a1.y;
        As[lcol + 2][lrow + 64] = a1.z; As[lcol + 3][lrow + 64] = a1.w;
        Bs[lcol + 0][lrow] = b0.x; Bs[lcol + 1][lrow] = b0.y;
        Bs[lcol + 2][lrow] = b0.z; Bs[lcol + 3][lrow] = b0.w;
        Bs[lcol + 0][lrow + 64] = b1.x; Bs[lcol + 1][lrow + 64] = b1.y;
        Bs[lcol + 2][lrow + 64] = b1.z; Bs[lcol + 3][lrow + 64] = b1.w;
        __syncthreads();
#pragma unroll
        for (int k = 0; k < BKK; ++k) {
            float ar[8];
            *(float4*)&ar[0] = *(const float4*)&As[k][ty * 8];
            *(float4*)&ar[4] = *(const float4*)&As[k][ty * 8 + 4];
            // B column pairs, read directly as packed 64-bit words (32B-aligned)
            ulonglong2 brA = *(const ulonglong2*)&Bs[k][tx * 8];
            ulonglong2 brB = *(const ulonglong2*)&Bs[k][tx * 8 + 4];
#pragma unroll
            for (int i = 0; i < 8; i++) {
                const unsigned long long a2 = pk2(ar[i], ar[i]);
                ffma2(acc2[i][0], a2, brA.x);
                ffma2(acc2[i][1], a2, brA.y);
                ffma2(acc2[i][2], a2, brB.x);
                ffma2(acc2[i][3], a2, brB.y);
            }
        }
    }
#pragma unroll
    for (int i = 0; i < 8; i++) {
        const size_t row = (size_t)bm * BM + ty * 8 + i;
        float* Cr = C + row * N + bn * BN + tx * 8;
        const float* bp = bias + bn * BN + tx * 8;
#pragma unroll
        for (int p = 0; p < 4; p++) {
            const float2 v = up2(acc2[i][p]);
            Cr[2 * p + 0] = v.x + bp[2 * p + 0];
            Cr[2 * p + 1] = v.y + bp[2 * p + 1];
        }
    }
}

// ---------------- scan init: seed tag buffers (runs before scan each launch) ----------------
__global__ void scan_init_kernel() {
    const int i = threadIdx.x;  // 512 threads
    st_rlx_u64(&g_hx8[0][i], pkht(0.0f, 0u));           // h(0)=0, tag 0
    st_rlx_u64(&g_hx8[1][i], pkht(0.0f, 0xFFFFFFFFu));  // sentinel
}

// ---------------- persistent GRU scan: 16 CTAs (R10 config), relaxed tagged L2 exchange ----------------
__global__ __launch_bounds__(256, 1) void gru_scan(const float* __restrict__ w_hh,
                                                   const float* __restrict__ b_n,
                                                   const float* __restrict__ igates,
                                                   float* __restrict__ hs,
                                                   float* h_final) {
    __shared__ __align__(16) float sh_h[2][NH];   // double-buffered staged h

    const int tid = threadIdx.x;
    const int gidx = tid >> 3, li = tid & 7;
    const int blk = blockIdx.x;
    const int j = blk * 32 + gidx;

    // preload weight slice into registers: rows (j, 512+j, 1024+j), cols li*4 + m*32 + {0..3}
    unsigned long long wr[32], wz[32], wn[32];
    {
        const float* br_ = w_hh + (size_t)j * NH + li * 4;
        const float* bz_ = w_hh + (size_t)(NH + j) * NH + li * 4;
        const float* bn_ = w_hh + (size_t)(2 * NH + j) * NH + li * 4;
#pragma unroll
        for (int m = 0; m < 16; m++) {
            float4 v = *(const float4*)(br_ + m * 32);
            wr[2 * m] = pk2(v.x, v.y); wr[2 * m + 1] = pk2(v.z, v.w);
            v = *(const float4*)(bz_ + m * 32);
            wz[2 * m] = pk2(v.x, v.y); wz[2 * m + 1] = pk2(v.z, v.w);
            v = *(const float4*)(bn_ + m * 32);
            wn[2 * m] = pk2(v.x, v.y); wn[2 * m + 1] = pk2(v.z, v.w);
        }
    }
    const float bnj = b_n[j];

    float igr = 0.f, igz = 0.f, ign = 0.f;
    if (li == 0) {
        igr = igates[j];
        igz = igates[NH + j];
        ign = igates[2 * NH + j];
    }

    for (int t = 0; t < NT; ++t) {
        const int buf = t & 1;
        // ---- consume: relaxed-poll my two (h, tag) words until both tags == t ----
        {
            const unsigned long long* gp = &g_hx8[buf][2 * tid];
            unsigned long long vx = ld_rlx_u64(gp);
            unsigned long long vy = ld_rlx_u64(gp + 1);
            while (hx_tag(vx) != (unsigned)t || hx_tag(vy) != (unsigned)t) {
                vx = ld_rlx_u64(gp);
                vy = ld_rlx_u64(gp + 1);
            }
            ((float2*)sh_h[buf])[tid] = make_float2(hx_val(vx), hx_val(vy));
        }
        __syncthreads();

        // ---- matvec on staged h ----
        unsigned long long ar = 0ULL, az = 0ULL, an = 0ULL;
        const ulonglong2* hv2 = (const ulonglong2*)sh_h[buf];
#pragma unroll
        for (int m = 0; m < 16; m++) {
            const ulonglong2 h2 = hv2[li + 8 * m];
            ffma2(ar, wr[2 * m], h2.x); ffma2(ar, wr[2 * m + 1], h2.y);
            ffma2(az, wz[2 * m], h2.x); ffma2(az, wz[2 * m + 1], h2.y);
            ffma2(an, wn[2 * m], h2.x); ffma2(an, wn[2 * m + 1], h2.y);
        }
        float2 f;
        f = up2(ar); float sr = f.x + f.y;
        f = up2(az); float sz = f.x + f.y;
        f = up2(an); float sn = f.x + f.y;
#pragma unroll
        for (int off = 4; off; off >>= 1) {
            sr += __shfl_xor_sync(0xffffffffu, sr, off);
            sz += __shfl_xor_sync(0xffffffffu, sz, off);
            sn += __shfl_xor_sync(0xffffffffu, sn, off);
        }

        if (li == 0) {
            const float r = sigmoid_fast(igr + sr);
            const float z = sigmoid_fast(igz + sz);
            const float n = tanh_fast(ign + r * (sn + bnj));
            const float hprev = sh_h[buf][j];
            const float hnew = n + z * (hprev - n);
            if (t < NT - 1) {
                // publish FIRST (unordered => no stall behind other stores)
                st_rlx_u64(&g_hx8[buf ^ 1][j], pkht(hnew, (unsigned)(t + 1)));
            }
            hs[(size_t)t * NH + j] = hnew;
            if (t == NT - 1) {
                if (h_final != nullptr) h_final[j] = hnew;
            } else {
                const float* igp = igates + (size_t)(t + 1) * G3;
                igr = igp[j]; igz = igp[NH + j]; ign = igp[2 * NH + j];
            }
        }
    }
}

// ---------------- gelu (tanh approx, matches jax default) ----------------
__global__ __launch_bounds__(256) void gelu_kernel(const float* __restrict__ in,
                                                   float* __restrict__ outp) {
    const size_t i = (size_t)blockIdx.x * 256 + threadIdx.x;
    const float4 v = ((const float4*)in)[i];
    const float c0 = 0.7978845608028654f, c1 = 0.044715f;
    float4 o;
    o.x = 0.5f * v.x * (1.0f + tanhf(c0 * (v.x + c1 * v.x * v.x * v.x)));
    o.y = 0.5f * v.y * (1.0f + tanhf(c0 * (v.y + c1 * v.y * v.y * v.y)));
    o.z = 0.5f * v.z * (1.0f + tanhf(c0 * (v.z + c1 * v.z * v.z * v.z)));
    o.w = 0.5f * v.w * (1.0f + tanhf(c0 * (v.w + c1 * v.w * v.w * v.w)));
    ((float4*)outp)[i] = o;
}

// ---------------- final combine: out = x + y1 * sigmoid(y2) ----------------
__global__ __launch_bounds__(256) void combine_kernel(const float* __restrict__ x,
                                                      const float* __restrict__ y1,
                                                      const float* __restrict__ y2,
                                                      float* __restrict__ outp) {
    const size_t i = (size_t)blockIdx.x * 256 + threadIdx.x;
    const float4 xv = ((const float4*)x)[i];
    const float4 a = ((const float4*)y1)[i];
    const float4 s = ((const float4*)y2)[i];
    float4 o;
    o.x = xv.x + a.x * sigmoid_acc(s.x);
    o.y = xv.y + a.y * sigmoid_acc(s.y);
    o.z = xv.z + a.z * sigmoid_acc(s.z);
    o.w = xv.w + a.w * sigmoid_acc(s.w);
    ((float4*)outp)[i] = o;
}

// ---------------- launch ----------------
extern "C" void kernel_launch(void* const* d_in, const int* in_sizes, int n_in,
                              void* d_out, int out_size) {
    const float* x     = (const float*)d_in[0];
    const float* w_ih  = (const float*)d_in[1];
    const float* w_hh  = (const float*)d_in[2];
    const float* b     = (const float*)d_in[3];
    const float* b_n   = (const float*)d_in[4];
    const float* out_w  = (const float*)d_in[5];
    const float* out_b  = (const float*)d_in[6];
    const float* out2_w = (const float*)d_in[7];
    const float* out2_b = (const float*)d_in[8];
    const float* ln_w  = (const float*)d_in[9];
    const float* ln_b  = (const float*)d_in[10];

    float* outp = (float*)d_out;
    float* hfin = nullptr;
    float* ybase = outp;
    if (out_size == 512 + 16384 * 1024) {  // tuple (h_final, y) flattened
        hfin = outp;
        ybase = outp + 512;
    }

    void *p_xn, *p_ig, *p_hs, *p_g, *p_y1, *p_y2;
    cudaGetSymbolAddress(&p_xn, d_xn);
    cudaGetSymbolAddress(&p_ig, d_ig);
    cudaGetSymbolAddress(&p_hs, d_hs);
    cudaGetSymbolAddress(&p_g, d_g);
    cudaGetSymbolAddress(&p_y1, d_y1);
    cudaGetSymbolAddress(&p_y2, d_y2);

    scan_init_kernel<<<1, 512>>>();   // reseed tag buffers (replay-safe)
    ln_kernel<<<NT, 256>>>(x, ln_w, ln_b, (float*)p_xn);
    sgemm_nt<<<dim3(G3 / BN, NT / BM), 256>>>((const float*)p_xn, w_ih, b,
                                              (float*)p_ig, NT, G3, HID);
    gru_scan<<<SCAN_CTAS, 256>>>(w_hh, b_n, (const float*)p_ig, (float*)p_hs, hfin);
    gelu_kernel<<<(NT * NH) / (4 * 256), 256>>>((const float*)p_hs, (float*)p_g);
    sgemm_nt<<<dim3(HID / BN, NT / BM), 256>>>((const float*)p_g, out_w, out_b,
                                               (float*)p_y1, NT, HID, NH);
    sgemm_nt<<<dim3(HID / BN, NT / BM), 256>>>((const float*)p_g, out2_w, out2_b,
                                               (float*)p_y2, NT, HID, NH);
    combine_kernel<<<(NT * HID) / (4 * 256), 256>>>(x, (const float*)p_y1,
                                                    (const float*)p_y2, ybase);
}

// round 16
// speedup vs baseline: 1.2123x; 1.1220x over previous
#include <cuda_runtime.h>
#include <math.h>
#include <stdint.h>

#define NT 16384
#define HID 1024
#define NH 512
#define G3 1536
#define SCAN_CTAS 16
#define WORKER_CTAS 132
#define TOTAL_CTAS 148
#define BANDS 128          // NT / 128
#define G1_TILES_N 12      // G3 / BN
#define EPI_COLS 8         // HID / BN
#define BM 128
#define BN 128
#define BKK 16

// ---------------- scratch (device globals; no allocation) ----------------
__device__ __align__(16) float d_xn[NT * HID];   // layernormed x
__device__ __align__(16) float d_ig[NT * G3];    // igates
__device__ __align__(16) float d_hs[NT * NH];    // h trajectory
__device__ __align__(16) float d_y1[NT * HID];   // first epilogue GEMM staging

// tagged h exchange: g_hx8[buf][j] = (f32 h low 32b, u32 tag high 32b), relaxed-atomic.
__device__ __align__(16) unsigned long long g_hx8[2][NH];
// igates band-completion counters (12 tiles per 128-row band)
__device__ unsigned g_band_cnt[BANDS];
// per-state-slot scan progress, release-published every 128 steps
__device__ unsigned g_prog[NH];

// ---------------- small helpers ----------------
__device__ __forceinline__ void ffma2(unsigned long long& d, unsigned long long a, unsigned long long b) {
    asm volatile("fma.rn.f32x2 %0, %1, %2, %0;" : "+l"(d) : "l"(a), "l"(b));
}
__device__ __forceinline__ unsigned long long pk2(float lo, float hi) {
    unsigned long long r;
    asm("mov.b64 %0, {%1, %2};" : "=l"(r) : "f"(lo), "f"(hi));
    return r;
}
__device__ __forceinline__ float2 up2(unsigned long long v) {
    float lo, hi;
    asm("mov.b64 {%0, %1}, %2;" : "=f"(lo), "=f"(hi) : "l"(v));
    return make_float2(lo, hi);
}
__device__ __forceinline__ unsigned long long pkht(float h, unsigned tag) {
    unsigned long long r;
    asm("mov.b64 %0, {%1, %2};" : "=l"(r) : "f"(h), "r"(tag));
    return r;
}
__device__ __forceinline__ unsigned hx_tag(unsigned long long v) { return (unsigned)(v >> 32); }
__device__ __forceinline__ float hx_val(unsigned long long v) {
    float h; unsigned t;
    asm("mov.b64 {%0, %1}, %2;" : "=f"(h), "=r"(t) : "l"(v));
    (void)t;
    return h;
}
__device__ __forceinline__ float sigmoid_fast(float x) {
    return __fdividef(1.0f, 1.0f + __expf(-x));
}
__device__ __forceinline__ float tanh_fast(float x) {
    return __fdividef(2.0f, 1.0f + __expf(-2.0f * x)) - 1.0f;
}
__device__ __forceinline__ float gelu_fast(float v) {
    const float c0 = 0.7978845608028654f, c1 = 0.044715f;
    return 0.5f * v * (1.0f + tanh_fast(c0 * (v + c1 * v * v * v)));
}
__device__ __forceinline__ void st_rlx_u64(unsigned long long* p, unsigned long long v) {
    asm volatile("st.relaxed.gpu.global.u64 [%0], %1;" :: "l"(p), "l"(v) : "memory");
}
__device__ __forceinline__ unsigned long long ld_rlx_u64(const unsigned long long* p) {
    unsigned long long v;
    asm volatile("ld.relaxed.gpu.global.u64 %0, [%1];" : "=l"(v) : "l"(p) : "memory");
    return v;
}
__device__ __forceinline__ unsigned ld_acq_u32(const unsigned* p) {
    unsigned v;
    asm volatile("ld.acquire.gpu.global.u32 %0, [%1];" : "=r"(v) : "l"(p) : "memory");
    return v;
}
__device__ __forceinline__ void st_rel_u32(unsigned* p, unsigned v) {
    asm volatile("st.release.gpu.global.u32 [%0], %1;" :: "l"(p), "r"(v) : "memory");
}
__device__ __forceinline__ void st_rlx_u32(unsigned* p, unsigned v) {
    asm volatile("st.relaxed.gpu.global.u32 [%0], %1;" :: "l"(p), "r"(v) : "memory");
}
__device__ __forceinline__ void red_rel_add_u32(unsigned* p, unsigned v) {
    asm volatile("red.add.release.gpu.global.u32 [%0], %1;" :: "l"(p), "r"(v) : "memory");
}
__device__ __forceinline__ void nsleep(unsigned ns) {
    asm volatile("nanosleep.u32 %0;" :: "r"(ns));
}

// ---------------- LayerNorm ----------------
__global__ __launch_bounds__(256) void ln_kernel(const float* __restrict__ x,
                                                 const float* __restrict__ w,
                                                 const float* __restrict__ bb,
                                                 float* __restrict__ xn) {
    const int row = blockIdx.x;
    const int tid = threadIdx.x;
    const float4 v = ((const float4*)(x + (size_t)row * HID))[tid];
    float s = v.x + v.y + v.z + v.w;
    float q = v.x * v.x + v.y * v.y + v.z * v.z + v.w * v.w;
#pragma unroll
    for (int off = 16; off; off >>= 1) {
        s += __shfl_xor_sync(0xffffffffu, s, off);
        q += __shfl_xor_sync(0xffffffffu, q, off);
    }
    __shared__ float rs[8], rq[8];
    __shared__ float mu_s, rstd_s;
    const int wid = tid >> 5, lane = tid & 31;
    if (lane == 0) { rs[wid] = s; rq[wid] = q; }
    __syncthreads();
    if (tid == 0) {
        float S = 0.f, Q = 0.f;
#pragma unroll
        for (int i = 0; i < 8; i++) { S += rs[i]; Q += rq[i]; }
        float mu = S * (1.0f / HID);
        float var = Q * (1.0f / HID) - mu * mu;
        mu_s = mu;
        rstd_s = rsqrtf(var + 1e-5f);
    }
    __syncthreads();
    const float mu = mu_s, rstd = rstd_s;
    const float4 wv = ((const float4*)w)[tid];
    const float4 bv = ((const float4*)bb)[tid];
    float4 o;
    o.x = (v.x - mu) * rstd * wv.x + bv.x;
    o.y = (v.y - mu) * rstd * wv.y + bv.y;
    o.z = (v.z - mu) * rstd * wv.z + bv.z;
    o.w = (v.w - mu) * rstd * wv.w + bv.w;
    ((float4*)(xn + (size_t)row * HID))[tid] = o;
}

// ---------------- init: seed tags, reset gates (runs before fused kernel) ----------------
__global__ void scan_init_kernel() {
    const int i = threadIdx.x;  // 512 threads
    st_rlx_u64(&g_hx8[0][i], pkht(0.0f, 0u));
    st_rlx_u64(&g_hx8[1][i], pkht(0.0f, 0xFFFFFFFFu));
    st_rlx_u32(&g_prog[i], 0u);
    if (i < BANDS) st_rlx_u32(&g_band_cnt[i], 0u);
}

// ---------------- worker GEMM tile: 128x128, packed f32x2 ----------------
// A row-major (lda), B row-major (ldb == K), K multiple of 16.
// MODE 0: C = acc + bias.  MODE 1: Out = X + Y1 * sigmoid(acc + bias)  (strides = ldc)
template <bool GELU_A, int MODE>
__device__ void gemm_tile(const float* __restrict__ Ab, int lda,
                          const float* __restrict__ Bb, int K,
                          const float* __restrict__ bias_p,
                          float* __restrict__ Cp, int ldc,
                          const float* __restrict__ Xp,
                          const float* __restrict__ Y1p,
                          float* __restrict__ Outp,
                          char* smem) {
    float (*As)[BM] = (float(*)[BM])smem;
    float (*Bs)[BN] = (float(*)[BN])(smem + BKK * BM * 4);
    const int tid = threadIdx.x;
    const int lrow = tid >> 2;
    const int lcol = (tid & 3) << 2;
    const int tx = tid & 15, ty = tid >> 4;
    unsigned long long acc2[8][4];
#pragma unroll
    for (int i = 0; i < 8; i++)
#pragma unroll
        for (int p = 0; p < 4; p++) acc2[i][p] = 0ULL;

    for (int k0 = 0; k0 < K; k0 += BKK) {
        float4 a0 = *(const float4*)(Ab + (size_t)lrow * lda + k0 + lcol);
        float4 a1 = *(const float4*)(Ab + (size_t)(lrow + 64) * lda + k0 + lcol);
        const float4 b0 = *(const float4*)(Bb + (size_t)lrow * K + k0 + lcol);
        const float4 b1 = *(const float4*)(Bb + (size_t)(lrow + 64) * K + k0 + lcol);
        if (GELU_A) {
            a0.x = gelu_fast(a0.x); a0.y = gelu_fast(a0.y);
            a0.z = gelu_fast(a0.z); a0.w = gelu_fast(a0.w);
            a1.x = gelu_fast(a1.x); a1.y = gelu_fast(a1.y);
            a1.z = gelu_fast(a1.z); a1.w = gelu_fast(a1.w);
        }
        __syncthreads();
        As[lcol + 0][lrow] = a0.x; As[lcol + 1][lrow] = a0.y;
        As[lcol + 2][lrow] = a0.z; As[lcol + 3][lrow] = a0.w;
        As[lcol + 0][lrow + 64] = a1.x; As[lcol + 1][lrow + 64] = a1.y;
        As[lcol + 2][lrow + 64] = a1.z; As[lcol + 3][lrow + 64] = a1.w;
        Bs[lcol + 0][lrow] = b0.x; Bs[lcol + 1][lrow] = b0.y;
        Bs[lcol + 2][lrow] = b0.z; Bs[lcol + 3][lrow] = b0.w;
        Bs[lcol + 0][lrow + 64] = b1.x; Bs[lcol + 1][lrow + 64] = b1.y;
        Bs[lcol + 2][lrow + 64] = b1.z; Bs[lcol + 3][lrow + 64] = b1.w;
        __syncthreads();
#pragma unroll
        for (int k = 0; k < BKK; ++k) {
            float ar[8];
            *(float4*)&ar[0] = *(const float4*)&As[k][ty * 8];
            *(float4*)&ar[4] = *(const float4*)&As[k][ty * 8 + 4];
            ulonglong2 brA = *(const ulonglong2*)&Bs[k][tx * 8];
            ulonglong2 brB = *(const ulonglong2*)&Bs[k][tx * 8 + 4];
#pragma unroll
            for (int i = 0; i < 8; i++) {
                const unsigned long long a2 = pk2(ar[i], ar[i]);
                ffma2(acc2[i][0], a2, brA.x);
                ffma2(acc2[i][1], a2, brA.y);
                ffma2(acc2[i][2], a2, brB.x);
                ffma2(acc2[i][3], a2, brB.y);
            }
        }
    }
#pragma unroll
    for (int i = 0; i < 8; i++) {
        const size_t off = (size_t)(ty * 8 + i) * ldc + tx * 8;
#pragma unroll
        for (int p = 0; p < 4; p++) {
            const float2 v = up2(acc2[i][p]);
            const float bx = bias_p[tx * 8 + 2 * p];
            const float by = bias_p[tx * 8 + 2 * p + 1];
            if (MODE == 0) {
                Cp[off + 2 * p + 0] = v.x + bx;
                Cp[off + 2 * p + 1] = v.y + by;
            } else {
                Outp[off + 2 * p + 0] = Xp[off + 2 * p + 0] + Y1p[off + 2 * p + 0] * sigmoid_fast(v.x + bx);
                Outp[off + 2 * p + 1] = Xp[off + 2 * p + 1] + Y1p[off + 2 * p + 1] * sigmoid_fast(v.y + by);
            }
        }
    }
}

// ---------------- fused persistent kernel: 16 scan CTAs + 132 worker CTAs ----------------
__global__ __launch_bounds__(256, 1) void fused_kernel(
    const float* __restrict__ w_hh, const float* __restrict__ b_n,
    const float* __restrict__ w_ih, const float* __restrict__ bias_ih,
    const float* __restrict__ x,
    const float* __restrict__ out_w, const float* __restrict__ out_b,
    const float* __restrict__ out2_w, const float* __restrict__ out2_b,
    float* __restrict__ hs, float* __restrict__ igates,
    const float* __restrict__ xn, float* __restrict__ y1,
    float* __restrict__ ybase, float* h_final) {
    __shared__ __align__(16) char smem_raw[2 * BKK * BM * 4];  // 16KB, shared by both paths
    const int blk = blockIdx.x;
    const int tid = threadIdx.x;

    if (blk < SCAN_CTAS) {
        // ================= scan path (R10 protocol + igates gating + progress releases) =================
        float (*sh_h)[NH] = (float(*)[NH])smem_raw;  // [2][NH]
        const int gidx = tid >> 3, li = tid & 7;
        const int j = blk * 32 + gidx;

        unsigned long long wr[32], wz[32], wn[32];
        {
            const float* br_ = w_hh + (size_t)j * NH + li * 4;
            const float* bz_ = w_hh + (size_t)(NH + j) * NH + li * 4;
            const float* bn_ = w_hh + (size_t)(2 * NH + j) * NH + li * 4;
#pragma unroll
            for (int m = 0; m < 16; m++) {
                float4 v = *(const float4*)(br_ + m * 32);
                wr[2 * m] = pk2(v.x, v.y); wr[2 * m + 1] = pk2(v.z, v.w);
                v = *(const float4*)(bz_ + m * 32);
                wz[2 * m] = pk2(v.x, v.y); wz[2 * m + 1] = pk2(v.z, v.w);
                v = *(const float4*)(bn_ + m * 32);
                wn[2 * m] = pk2(v.x, v.y); wn[2 * m + 1] = pk2(v.z, v.w);
            }
        }
        const float bnj = b_n[j];

        float igr = 0.f, igz = 0.f, ign = 0.f;
        unsigned ready_rows = 0;
        if (li == 0) {
            while (ld_acq_u32(&g_band_cnt[0]) < (unsigned)G1_TILES_N) {}  // band 0 ready
            ready_rows = 128;
            igr = igates[j];
            igz = igates[NH + j];
            ign = igates[2 * NH + j];
        }

        for (int t = 0; t < NT; ++t) {
            const int buf = t & 1;
            {
                const unsigned long long* gp = &g_hx8[buf][2 * tid];
                unsigned long long vx = ld_rlx_u64(gp);
                unsigned long long vy = ld_rlx_u64(gp + 1);
                while (hx_tag(vx) != (unsigned)t || hx_tag(vy) != (unsigned)t) {
                    vx = ld_rlx_u64(gp);
                    vy = ld_rlx_u64(gp + 1);
                }
                ((float2*)sh_h[buf])[tid] = make_float2(hx_val(vx), hx_val(vy));
            }
            __syncthreads();

            unsigned long long ar = 0ULL, az = 0ULL, an = 0ULL;
            const ulonglong2* hv2 = (const ulonglong2*)sh_h[buf];
#pragma unroll
            for (int m = 0; m < 16; m++) {
                const ulonglong2 h2 = hv2[li + 8 * m];
                ffma2(ar, wr[2 * m], h2.x); ffma2(ar, wr[2 * m + 1], h2.y);
                ffma2(az, wz[2 * m], h2.x); ffma2(az, wz[2 * m + 1], h2.y);
                ffma2(an, wn[2 * m], h2.x); ffma2(an, wn[2 * m + 1], h2.y);
            }
            float2 f;
            f = up2(ar); float sr = f.x + f.y;
            f = up2(az); float sz = f.x + f.y;
            f = up2(an); float sn = f.x + f.y;
#pragma unroll
            for (int off = 4; off; off >>= 1) {
                sr += __shfl_xor_sync(0xffffffffu, sr, off);
                sz += __shfl_xor_sync(0xffffffffu, sz, off);
                sn += __shfl_xor_sync(0xffffffffu, sn, off);
            }

            if (li == 0) {
                const float r = sigmoid_fast(igr + sr);
                const float z = sigmoid_fast(igz + sz);
                const float n = tanh_fast(ign + r * (sn + bnj));
                const float hprev = sh_h[buf][j];
                const float hnew = n + z * (hprev - n);
                if (t < NT - 1) {
                    st_rlx_u64(&g_hx8[buf ^ 1][j], pkht(hnew, (unsigned)(t + 1)));  // publish first
                }
                hs[(size_t)t * NH + j] = hnew;
                if (t == NT - 1 && h_final != nullptr) h_final[j] = hnew;
                if (((t + 1) & 127) == 0) {
                    st_rel_u32(&g_prog[j], (unsigned)(t + 1));  // orders all prior hs stores
                }
                if (t < NT - 1) {
                    const int tn = t + 1;
                    if ((unsigned)tn >= ready_rows) {
                        while (ld_acq_u32(&g_band_cnt[tn >> 7]) < (unsigned)G1_TILES_N) {}
                        ready_rows += 128;
                    }
                    const float* igp = igates + (size_t)tn * G3;
                    igr = igp[j]; igz = igp[NH + j]; ign = igp[2 * NH + j];
                }
            }
        }
    } else {
        // ================= worker path =================
        const int wid = blk - SCAN_CTAS;

        // phase 1: GEMM1  igates = xn @ w_ih^T + b   (band-major order)
        for (int item = wid; item < BANDS * G1_TILES_N; item += WORKER_CTAS) {
            const int bm = item / G1_TILES_N, bn = item % G1_TILES_N;
            gemm_tile<false, 0>(xn + (size_t)bm * 128 * HID, HID,
                                w_ih + (size_t)bn * 128 * HID, HID,
                                bias_ih + bn * 128,
                                igates + (size_t)bm * 128 * G3 + bn * 128, G3,
                                nullptr, nullptr, nullptr, smem_raw);
            __syncthreads();
            if (tid == 0) red_rel_add_u32(&g_band_cnt[bm], 1u);
        }

        // phase 2: epilogue  out = x + (g@out_w^T+out_b) * sigmoid(g@out2_w^T+out2_b), g = gelu(hs)
        for (int item = wid; item < BANDS * EPI_COLS; item += WORKER_CTAS) {
            const int b = item / EPI_COLS, c = item % EPI_COLS;
            const unsigned target = (unsigned)(b + 1) * 128u;
            // coarse gate (one thread, backoff) then full acquire verification
            if (tid == 0) {
                while (ld_acq_u32(&g_prog[0]) < target) nsleep(2000);
            }
            __syncthreads();
            while (ld_acq_u32(&g_prog[2 * tid]) < target) {}
            while (ld_acq_u32(&g_prog[2 * tid + 1]) < target) {}
            __syncthreads();

            const int r0 = b * 128, n0 = c * 128;
            gemm_tile<true, 0>(hs + (size_t)r0 * NH, NH,
                               out_w + (size_t)n0 * NH, NH,
                               out_b + n0,
                               y1 + (size_t)r0 * HID + n0, HID,
                               nullptr, nullptr, nullptr, smem_raw);
            __syncthreads();
            gemm_tile<true, 1>(hs + (size_t)r0 * NH, NH,
                               out2_w + (size_t)n0 * NH, NH,
                               out2_b + n0,
                               nullptr, HID,
                               x + (size_t)r0 * HID + n0,
                               y1 + (size_t)r0 * HID + n0,
                               ybase + (size_t)r0 * HID + n0, smem_raw);
            __syncthreads();
        }
    }
}

// ---------------- launch ----------------
extern "C" void kernel_launch(void* const* d_in, const int* in_sizes, int n_in,
                              void* d_out, int out_size) {
    const float* x     = (const float*)d_in[0];
    const float* w_ih  = (const float*)d_in[1];
    const float* w_hh  = (const float*)d_in[2];
    const float* b     = (const float*)d_in[3];
    const float* b_n   = (const float*)d_in[4];
    const float* out_w  = (const float*)d_in[5];
    const float* out_b  = (const float*)d_in[6];
    const float* out2_w = (const float*)d_in[7];
    const float* out2_b = (const float*)d_in[8];
    const float* ln_w  = (const float*)d_in[9];
    const float* ln_b  = (const float*)d_in[10];

    float* outp = (float*)d_out;
    float* hfin = nullptr;
    float* ybase = outp;
    if (out_size == 512 + 16384 * 1024) {  // tuple (h_final, y) flattened
        hfin = outp;
        ybase = outp + 512;
    }

    void *p_xn, *p_ig, *p_hs, *p_y1;
    cudaGetSymbolAddress(&p_xn, d_xn);
    cudaGetSymbolAddress(&p_ig, d_ig);
    cudaGetSymbolAddress(&p_hs, d_hs);
    cudaGetSymbolAddress(&p_y1, d_y1);

    scan_init_kernel<<<1, 512>>>();   // reseed tags + gates (replay-safe)
    ln_kernel<<<NT, 256>>>(x, ln_w, ln_b, (float*)p_xn);
    fused_kernel<<<TOTAL_CTAS, 256>>>(
        w_hh, b_n, w_ih, b, x, out_w, out_b, out2_w, out2_b,
        (float*)p_hs, (float*)p_ig, (const float*)p_xn, (float*)p_y1,
        ybase, hfin);
}